// round 11
// baseline (speedup 1.0000x reference)
#include <cuda_runtime.h>
#include <cstdint>

#define D 64
#define NMAX 100000
#define EMAX 1664000

// ---------------------------------------------------------------------------
// Device scratch
// ---------------------------------------------------------------------------
__device__ uint2   g_rec[EMAX];               // CSR records: (src, w bits)
__device__ int     g_cnt[NMAX];               // histogram / write cursors
__device__ int     g_off[NMAX + 1];           // CSR row offsets
__device__ int     g_blk[128];                // block totals for scan
__device__ uint8_t g_Bimg[139264];            // bf16 hi+lo weight image (grouped cols)
__device__ float   g_biasf[256];              // biases: [r(64)|z(64)|i_n(64)|h_n(64)]
__device__ int     g_is32;                    // src/dst dtype flag

// SMEM map for the GEMM kernel
#define STRIDE_A 272            // 128 k * 2B padded to 17*16B (ldmatrix conflict-free)
#define A_HALF_W 4352           // per-warp A half: 16 rows * 272
#define A_WARP   8704           // per-warp A region (hi + lo)
#define B_HALF   69632          // 256 rows * 272
#define SM_BIAS  0
#define SM_A     1024
#define SM_B     (SM_A + 8 * A_WARP)          // 70656
#define SM_TOT   (SM_B + 2 * B_HALF)          // 209920

// ---------------------------------------------------------------------------
// Helpers
// ---------------------------------------------------------------------------
__device__ __forceinline__ uint32_t smem_u32(const void* p) {
    uint32_t a;
    asm("{ .reg .u64 t; cvta.to.shared.u64 t, %1; cvt.u32.u64 %0, t; }"
        : "=r"(a) : "l"(p));
    return a;
}
__device__ __forceinline__ uint32_t cvtbf2(float hi, float lo) {
    uint32_t d;
    asm("cvt.rn.bf16x2.f32 %0, %1, %2;" : "=r"(d) : "f"(hi), "f"(lo));
    return d;
}
__device__ __forceinline__ float bflo_f(uint32_t p) { return __uint_as_float(p << 16); }
__device__ __forceinline__ float bfhi_f(uint32_t p) { return __uint_as_float(p & 0xffff0000u); }

__device__ __forceinline__ float sigmoidf_fast(float x) {
    return __fdividef(1.0f, 1.0f + __expf(-x));
}
__device__ __forceinline__ float tanhf_fast(float x) {
    return 1.0f - __fdividef(2.0f, __expf(2.0f * x) + 1.0f);
}

#define LDSM4(r0, r1, r2, r3, a)                                            \
    asm volatile("ldmatrix.sync.aligned.m8n8.x4.shared.b16 {%0,%1,%2,%3}, [%4];" \
                 : "=r"(r0), "=r"(r1), "=r"(r2), "=r"(r3) : "r"(a))

#define MMA16816(c, a0, a1, a2, a3, b0, b1)                                 \
    asm volatile("mma.sync.aligned.m16n8k16.row.col.f32.bf16.bf16.f32 "     \
                 "{%0,%1,%2,%3}, {%4,%5,%6,%7}, {%8,%9}, {%0,%1,%2,%3};"    \
                 : "+f"((c)[0]), "+f"((c)[1]), "+f"((c)[2]), "+f"((c)[3])   \
                 : "r"(a0), "r"(a1), "r"(a2), "r"(a3), "r"(b0), "r"(b1))

// ---------------------------------------------------------------------------
// zcnt (+ fused index-dtype detection in block 0)
// ---------------------------------------------------------------------------
__global__ void zcnt_kernel(const unsigned long long* __restrict__ src,
                            const unsigned long long* __restrict__ dst, int Nn) {
    int i = blockIdx.x * blockDim.x + threadIdx.x;
    if (i < Nn) g_cnt[i] = 0;
    if (i == 0) {
        unsigned long long acc = 0;
#pragma unroll
        for (int k = 0; k < 8; k++) acc |= (src[k] >> 32) | (dst[k] >> 32);
        g_is32 = (acc != 0ULL) ? 1 : 0;
    }
}

__global__ void hist_kernel(const void* __restrict__ dstp, int E) {
    int e = blockIdx.x * blockDim.x + threadIdx.x;
    if (e >= E) return;
    int d = g_is32 ? ((const int*)dstp)[e]
                   : (int)((const long long*)dstp)[e];
    atomicAdd(&g_cnt[d], 1);
}

// Hierarchical scan A: 1024-wide block scan; g_off = within-block exclusive.
__global__ void __launch_bounds__(1024) scanA_kernel(int Nn) {
    __shared__ int ws[32];
    const int t = threadIdx.x, lane = t & 31, wid = t >> 5;
    const int i = blockIdx.x * 1024 + t;
    int c = (i < Nn) ? g_cnt[i] : 0;
    int v = c;
#pragma unroll
    for (int d = 1; d < 32; d <<= 1) {
        int n = __shfl_up_sync(0xffffffffu, v, d);
        if (lane >= d) v += n;
    }
    if (lane == 31) ws[wid] = v;
    __syncthreads();
    if (wid == 0) {
        int wv = ws[lane];
#pragma unroll
        for (int d = 1; d < 32; d <<= 1) {
            int n = __shfl_up_sync(0xffffffffu, wv, d);
            if (lane >= d) wv += n;
        }
        ws[lane] = wv;
    }
    __syncthreads();
    int incl = v + (wid ? ws[wid - 1] : 0);
    if (i < Nn) g_off[i] = incl - c;
    if (t == 1023) g_blk[blockIdx.x] = incl;
}

// scanC (with scanB folded in): each 256-thread block covers one aligned
// 256-range of i, which maps to a single 1024-block index; the block
// redundantly reduces the preceding block totals (<=127 adds) itself.
__global__ void __launch_bounds__(256) scanC_kernel(int Nn, int E) {
    __shared__ int ssum[8];
    const int t = threadIdx.x, lane = t & 31, wid = t >> 5;
    const int myblk = blockIdx.x >> 2;             // 1024-block this range is in
    int v = (t < 128 && t < myblk) ? g_blk[t] : 0;
#pragma unroll
    for (int d = 16; d > 0; d >>= 1) v += __shfl_down_sync(0xffffffffu, v, d);
    if (lane == 0) ssum[wid] = v;
    __syncthreads();
    int blkoff = ssum[0] + ssum[1] + ssum[2] + ssum[3];

    int i = blockIdx.x * 256 + t;
    if (i < Nn) {
        int off = g_off[i] + blkoff;
        g_off[i] = off;
        g_cnt[i] = off;
    }
    if (i == 0) g_off[Nn] = E;
}

__global__ void reorder_kernel(const void* __restrict__ srcp,
                               const void* __restrict__ dstp,
                               const float* __restrict__ ew, int E) {
    int e = blockIdx.x * blockDim.x + threadIdx.x;
    if (e >= E) return;
    int s, d;
    if (g_is32) {
        s = ((const int*)srcp)[e];
        d = ((const int*)dstp)[e];
    } else {
        s = (int)((const long long*)srcp)[e];
        d = (int)((const long long*)dstp)[e];
    }
    int pos = atomicAdd(&g_cnt[d], 1);
    g_rec[pos] = make_uint2((uint32_t)s, __float_as_uint(__ldg(&ew[e])));
}

// ---------------------------------------------------------------------------
// prep — bf16 hi/lo weight image, GROUPED col order [r|z|i_n|h_n], + biases.
// ---------------------------------------------------------------------------
__global__ void prep_kernel(const float* __restrict__ Wih,
                            const float* __restrict__ Whh,
                            const float* __restrict__ bih,
                            const float* __restrict__ bhh) {
    int idx = blockIdx.x * blockDim.x + threadIdx.x;   // 256 cols' x 32 quads
    if (idx < 8192) {
        int colp = idx >> 5, q = idx & 31;
        int g = colp >> 6, j = colp & 63;
        int kk = (q & 15) * 4;
        bool isX = (q < 16);
        float4 v = make_float4(0.f, 0.f, 0.f, 0.f);
        const float* srcRow = nullptr;
        if (g == 0)      srcRow = isX ? &Wih[j * 64]         : &Whh[j * 64];
        else if (g == 1) srcRow = isX ? &Wih[(64 + j) * 64]  : &Whh[(64 + j) * 64];
        else if (g == 2) srcRow = isX ? &Wih[(128 + j) * 64] : nullptr;
        else             srcRow = isX ? nullptr              : &Whh[(128 + j) * 64];
        if (srcRow) v = *(const float4*)(srcRow + kk);

        uint32_t h01 = cvtbf2(v.y, v.x), h23 = cvtbf2(v.w, v.z);
        uint32_t l01 = cvtbf2(v.y - bfhi_f(h01), v.x - bflo_f(h01));
        uint32_t l23 = cvtbf2(v.w - bfhi_f(h23), v.z - bflo_f(h23));
        uint32_t off = (uint32_t)colp * STRIDE_A + ((q >> 1) << 4) + ((q & 1) << 3);
        *(uint2*)(g_Bimg + off)          = make_uint2(h01, h23);
        *(uint2*)(g_Bimg + off + B_HALF) = make_uint2(l01, l23);
    }
    if (idx < 64) {
        g_biasf[idx]       = bih[idx] + bhh[idx];
        g_biasf[64 + idx]  = bih[64 + idx] + bhh[64 + idx];
        g_biasf[128 + idx] = bih[128 + idx];
        g_biasf[192 + idx] = bhh[128 + idx];
    }
}

// ---------------------------------------------------------------------------
// FUSED gather + GEMM + GRU epilogue: warp-independent 16-row tiles.
// A-prep phase A: each half-warp gathers one node's CSR edges and accumulates
// h_new in registers (lane = one float4 part), writes bf16 hi/lo to SMEM.
// No g_hnew4 round-trip; gather latency hides under other warps' MMAs.
// ---------------------------------------------------------------------------
#define GEMM_STEP(S, NB, GRP)                                                  \
    do {                                                                       \
        uint32_t b0, b1, b2, b3;                                               \
        LDSM4(b0, b1, b2, b3,                                                  \
              bbase_##GRP + (uint32_t)(NB) * (16 * STRIDE_A) + (uint32_t)(S) * 32); \
        float* c0 = &acc[((NB) * 2) * 4];                                      \
        float* c1 = &acc[((NB) * 2 + 1) * 4];                                  \
        MMA16816(c0, ah0, ah1, ah2, ah3, b0, b1);                              \
        MMA16816(c1, ah0, ah1, ah2, ah3, b2, b3);                              \
        if (GRP == 0) {                                                        \
            MMA16816(c0, al0, al1, al2, al3, b0, b1);                          \
            MMA16816(c1, al0, al1, al2, al3, b2, b3);                          \
        }                                                                      \
    } while (0)

__global__ void __launch_bounds__(256, 1)
gemm_gru_kernel(const float4* __restrict__ h4, float* __restrict__ out,
                int Nn, int n_tiles16) {
    extern __shared__ __align__(16) char smem[];
    const uint32_t sb = smem_u32(smem);
    const int tid = threadIdx.x;
    const int w = tid >> 5, l = tid & 31;
    const int r0q = l >> 2, tg = l & 3;
    const int halfsel = l >> 4, p = l & 15;

    // --- B image + bias -> SMEM ---
    {
        const uint4* srcB = (const uint4*)g_Bimg;
        uint4* dstB = (uint4*)(smem + SM_B);
        for (int i = tid; i < (2 * B_HALF) / 16; i += 256) dstB[i] = srcB[i];
        ((float*)smem)[tid] = g_biasf[tid];
    }
    __syncthreads();

    const int warpA_off = SM_A + w * A_WARP;
    const int sel = l >> 3;
    const uint32_t a_base = sb + (uint32_t)warpA_off +
        (uint32_t)((((sel & 1) << 3) + (l & 7)) * STRIDE_A + ((sel >> 1) << 4));
    const uint32_t b_base = sb + SM_B +
        (uint32_t)((((sel >> 1) << 3) + (l & 7)) * STRIDE_A + ((sel & 1) << 4));

    for (int tw = blockIdx.x * 8 + w; tw < n_tiles16; tw += gridDim.x * 8) {
        const int m0 = tw << 4;

        // --- A-prep phase A: fused CSR gather -> h_new quads 0..15 ---
#pragma unroll 1
        for (int ii = 0; ii < 8; ii++) {
            const int row = ii * 2 + halfsel;
            const int node = m0 + row;
            float4 a4 = make_float4(0.f, 0.f, 0.f, 0.f);
            if (node < Nn) {
                int e = g_off[node];
                const int end = g_off[node + 1];
                for (; e + 4 <= end; e += 4) {
                    uint2 r0 = g_rec[e],     r1 = g_rec[e + 1];
                    uint2 r2 = g_rec[e + 2], r3 = g_rec[e + 3];
                    float4 v0 = __ldg(&h4[(size_t)r0.x * 16 + p]);
                    float4 v1 = __ldg(&h4[(size_t)r1.x * 16 + p]);
                    float4 v2 = __ldg(&h4[(size_t)r2.x * 16 + p]);
                    float4 v3 = __ldg(&h4[(size_t)r3.x * 16 + p]);
                    float w0 = __uint_as_float(r0.y), w1 = __uint_as_float(r1.y);
                    float w2 = __uint_as_float(r2.y), w3 = __uint_as_float(r3.y);
                    a4.x = fmaf(v0.x, w0, a4.x); a4.y = fmaf(v0.y, w0, a4.y);
                    a4.z = fmaf(v0.z, w0, a4.z); a4.w = fmaf(v0.w, w0, a4.w);
                    a4.x = fmaf(v1.x, w1, a4.x); a4.y = fmaf(v1.y, w1, a4.y);
                    a4.z = fmaf(v1.z, w1, a4.z); a4.w = fmaf(v1.w, w1, a4.w);
                    a4.x = fmaf(v2.x, w2, a4.x); a4.y = fmaf(v2.y, w2, a4.y);
                    a4.z = fmaf(v2.z, w2, a4.z); a4.w = fmaf(v2.w, w2, a4.w);
                    a4.x = fmaf(v3.x, w3, a4.x); a4.y = fmaf(v3.y, w3, a4.y);
                    a4.z = fmaf(v3.z, w3, a4.z); a4.w = fmaf(v3.w, w3, a4.w);
                }
                for (; e < end; e++) {
                    uint2 r = g_rec[e];
                    float4 v = __ldg(&h4[(size_t)r.x * 16 + p]);
                    float wv = __uint_as_float(r.y);
                    a4.x = fmaf(v.x, wv, a4.x); a4.y = fmaf(v.y, wv, a4.y);
                    a4.z = fmaf(v.z, wv, a4.z); a4.w = fmaf(v.w, wv, a4.w);
                }
            }
            uint32_t h01 = cvtbf2(a4.y, a4.x), h23 = cvtbf2(a4.w, a4.z);
            uint32_t l01 = cvtbf2(a4.y - bfhi_f(h01), a4.x - bflo_f(h01));
            uint32_t l23 = cvtbf2(a4.w - bfhi_f(h23), a4.z - bflo_f(h23));
            uint32_t off = (uint32_t)warpA_off + (uint32_t)row * STRIDE_A +
                           ((uint32_t)(p >> 1) << 4) + ((uint32_t)(p & 1) << 3);
            *(uint2*)(smem + off)            = make_uint2(h01, h23);
            *(uint2*)(smem + off + A_HALF_W) = make_uint2(l01, l23);
        }
        // --- A-prep phase B: h rows -> quads 16..31 ---
#pragma unroll
        for (int ii = 0; ii < 8; ii++) {
            const int row = ii * 2 + halfsel;
            const int node = m0 + row;
            const int kq = 16 + p;
            float4 v = make_float4(0.f, 0.f, 0.f, 0.f);
            if (node < Nn) v = __ldg(&h4[node * 16 + p]);
            uint32_t h01 = cvtbf2(v.y, v.x), h23 = cvtbf2(v.w, v.z);
            uint32_t l01 = cvtbf2(v.y - bfhi_f(h01), v.x - bflo_f(h01));
            uint32_t l23 = cvtbf2(v.w - bfhi_f(h23), v.z - bflo_f(h23));
            uint32_t off = (uint32_t)warpA_off + (uint32_t)row * STRIDE_A +
                           ((uint32_t)(kq >> 1) << 4) + ((uint32_t)(kq & 1) << 3);
            *(uint2*)(smem + off)            = make_uint2(h01, h23);
            *(uint2*)(smem + off + A_HALF_W) = make_uint2(l01, l23);
        }
        __syncwarp();

        float acc[128];
#pragma unroll
        for (int i = 0; i < 128; i++) acc[i] = 0.f;

        // ---- group 0: (Ahi + Alo) x Bhi ----
        {
            const uint32_t bbase_0 = b_base;
#pragma unroll 1
            for (int s = 0; s < 4; s++) {          // low-k: r,z + i_n
                uint32_t ah0, ah1, ah2, ah3, al0, al1, al2, al3;
                LDSM4(ah0, ah1, ah2, ah3, a_base + (uint32_t)s * 32);
                LDSM4(al0, al1, al2, al3, a_base + A_HALF_W + (uint32_t)s * 32);
#pragma unroll
                for (int q = 0; q < 12; q++) GEMM_STEP(s, q, 0);
            }
#pragma unroll 1
            for (int s = 4; s < 8; s++) {          // high-k: r,z + h_n
                uint32_t ah0, ah1, ah2, ah3, al0, al1, al2, al3;
                LDSM4(ah0, ah1, ah2, ah3, a_base + (uint32_t)s * 32);
                LDSM4(al0, al1, al2, al3, a_base + A_HALF_W + (uint32_t)s * 32);
#pragma unroll
                for (int q = 0; q < 12; q++) { int nb = (q < 8) ? q : q + 4; GEMM_STEP(s, nb, 0); }
            }
        }
        // ---- group 1: Ahi x Blo ----
        {
            const uint32_t bbase_1 = b_base + B_HALF;
#pragma unroll 1
            for (int s = 0; s < 4; s++) {
                uint32_t ah0, ah1, ah2, ah3;
                uint32_t al0 = 0, al1 = 0, al2 = 0, al3 = 0; (void)al0;
                LDSM4(ah0, ah1, ah2, ah3, a_base + (uint32_t)s * 32);
#pragma unroll
                for (int q = 0; q < 12; q++) GEMM_STEP(s, q, 1);
            }
#pragma unroll 1
            for (int s = 4; s < 8; s++) {
                uint32_t ah0, ah1, ah2, ah3;
                uint32_t al0 = 0, al1 = 0, al2 = 0, al3 = 0; (void)al0;
                LDSM4(ah0, ah1, ah2, ah3, a_base + (uint32_t)s * 32);
#pragma unroll
                for (int q = 0; q < 12; q++) { int nb = (q < 8) ? q : q + 4; GEMM_STEP(s, nb, 1); }
            }
        }

        // --- Epilogue phase 1: gate math (no shuffles) ---
#pragma unroll
        for (int rs = 0; rs < 2; rs++) {
            const int node_local = r0q + rs * 8;
#pragma unroll
            for (int fn = 0; fn < 8; fn++) {
                const uint32_t bj = (uint32_t)((fn * 8 + tg * 2) * 4);
                float2 br = *(const float2*)(smem + SM_BIAS + bj);
                float2 bz = *(const float2*)(smem + SM_BIAS + 256 + bj);
                float2 bi = *(const float2*)(smem + SM_BIAS + 512 + bj);
                float2 bh = *(const float2*)(smem + SM_BIAS + 768 + bj);
#pragma unroll
                for (int b = 0; b < 2; b++) {
                    int j = fn * 8 + tg * 2 + b;
                    float rp = acc[fn * 4 + 2 * rs + b];
                    float zp = acc[(fn + 8) * 4 + 2 * rs + b];
                    float ip = acc[(fn + 16) * 4 + 2 * rs + b];
                    float hp = acc[(fn + 24) * 4 + 2 * rs + b];
                    float rr = sigmoidf_fast(rp + (b ? br.y : br.x));
                    float zz = sigmoidf_fast(zp + (b ? bz.y : bz.x));
                    float nn = tanhf_fast(ip + (b ? bi.y : bi.x) +
                                          rr * (hp + (b ? bh.y : bh.x)));
                    int kcol = 64 + j;
                    uint32_t hoff = (uint32_t)warpA_off +
                                    (uint32_t)node_local * STRIDE_A +
                                    ((uint32_t)(kcol >> 3) << 4) +
                                    ((uint32_t)(kcol & 7) << 1);
                    uint32_t hib = *(const unsigned short*)(smem + hoff);
                    uint32_t lob = *(const unsigned short*)(smem + hoff + A_HALF_W);
                    float hv = __uint_as_float(hib << 16) + __uint_as_float(lob << 16);
                    acc[fn * 4 + 2 * rs + b] = (1.f - zz) * nn + zz * hv;
                }
            }
        }
        __syncwarp();

        // --- Epilogue phase 2: stage float2 into warp-private SMEM (XOR sw) ---
#pragma unroll
        for (int rs = 0; rs < 2; rs++) {
            const int nl = r0q + rs * 8;
            const uint32_t sw = ((uint32_t)(nl & 7)) << 2;
#pragma unroll
            for (int fn = 0; fn < 8; fn++) {
                uint32_t u = (uint32_t)(fn * 4 + tg);
                uint32_t sa = (uint32_t)warpA_off + (uint32_t)nl * 256 +
                              ((u ^ sw) << 3);
                *(float2*)(smem + sa) =
                    make_float2(acc[fn * 4 + 2 * rs], acc[fn * 4 + 2 * rs + 1]);
            }
        }
        __syncwarp();

        // --- Epilogue phase 3: coalesced 16B stores ---
#pragma unroll
        for (int it = 0; it < 8; it++) {
            int idx = it * 32 + l;
            int nl = idx >> 4, c16 = idx & 15;
            uint32_t ra = (uint32_t)warpA_off + (uint32_t)nl * 256 +
                          ((uint32_t)(c16 ^ ((nl & 7) << 1)) << 4);
            float4 v = *(const float4*)(smem + ra);
            int node = m0 + nl;
            if (node < Nn) *(float4*)(out + (size_t)node * 64 + c16 * 4) = v;
        }
        __syncwarp();
    }
}

// ---------------------------------------------------------------------------
// Launch
// ---------------------------------------------------------------------------
extern "C" void kernel_launch(void* const* d_in, const int* in_sizes, int n_in,
                              void* d_out, int out_size) {
    const float* h   = (const float*)d_in[0];
    const float* ew  = (const float*)d_in[1];
    const float* Wih = (const float*)d_in[2];
    const float* Whh = (const float*)d_in[3];
    const float* bih = (const float*)d_in[4];
    const float* bhh = (const float*)d_in[5];
    const void* srcp = d_in[6];
    const void* dstp = d_in[7];
    float* out       = (float*)d_out;

    int E  = in_sizes[1];
    int Nn = in_sizes[0] / D;
    int n_tiles16 = (Nn + 15) / 16;
    int eblocks = (E + 255) / 256;
    int nb = (Nn + 1023) / 1024;

    zcnt_kernel<<<(Nn + 255) / 256, 256>>>((const unsigned long long*)srcp,
                                           (const unsigned long long*)dstp, Nn);
    hist_kernel<<<eblocks, 256>>>(dstp, E);
    scanA_kernel<<<nb, 1024>>>(Nn);
    scanC_kernel<<<(Nn + 255) / 256, 256>>>(Nn, E);
    reorder_kernel<<<eblocks, 256>>>(srcp, dstp, ew, E);

    prep_kernel<<<32, 256>>>(Wih, Whh, bih, bhh);

    cudaFuncSetAttribute(gemm_gru_kernel,
                         cudaFuncAttributeMaxDynamicSharedMemorySize, SM_TOT);
    gemm_gru_kernel<<<148, 256, SM_TOT>>>((const float4*)h, out, Nn, n_tiles16);
}

// round 12
// speedup vs baseline: 1.4894x; 1.4894x over previous
#include <cuda_runtime.h>
#include <cuda_fp16.h>
#include <cstdint>

#define D 64
#define NMAX 100000
#define EMAX 1664000

// ---------------------------------------------------------------------------
// Device scratch
// ---------------------------------------------------------------------------
__device__ float4  g_hnew4[NMAX * (D / 4)];   // h_new result (25.6 MB)
__device__ uint2   g_rec[EMAX];               // CSR records: (src, w bits)
__device__ int     g_cnt[NMAX];               // histogram / write cursors
__device__ int     g_off[NMAX + 1];           // CSR row offsets
__device__ int     g_blk[128];                // block totals for scan
__device__ uint8_t g_Bimg[69632];             // fp16 weight image (grouped cols)
__device__ float   g_biasf[256];              // biases: [r(64)|z(64)|i_n(64)|h_n(64)]
__device__ int     g_is32;                    // src/dst dtype flag

// SMEM map for the GEMM kernel
#define STRIDE_A 272            // 128 k * 2B padded to 17*16B (ldmatrix conflict-free)
#define A_HALF_W 4352           // per-warp A half: 16 rows * 272
#define A_WARP   8704           // per-warp A region (hi + lo)
#define B_IMG    69632          // 256 rows * 272 (single fp16 image)
#define SM_BIAS  0
#define SM_A     1024
#define SM_B     (SM_A + 8 * A_WARP)          // 70656
#define SM_TOT   (SM_B + B_IMG)               // 140288

// ---------------------------------------------------------------------------
// Helpers
// ---------------------------------------------------------------------------
__device__ __forceinline__ uint32_t smem_u32(const void* p) {
    uint32_t a;
    asm("{ .reg .u64 t; cvta.to.shared.u64 t, %1; cvt.u32.u64 %0, t; }"
        : "=r"(a) : "l"(p));
    return a;
}
// pack two f32 into f16x2: result {lo=b, hi=a}
__device__ __forceinline__ uint32_t cvth2(float hi, float lo) {
    uint32_t d;
    asm("cvt.rn.f16x2.f32 %0, %1, %2;" : "=r"(d) : "f"(hi), "f"(lo));
    return d;
}
__device__ __forceinline__ float f16lo_f(uint32_t p) {
    float f; unsigned short s = (unsigned short)(p & 0xffffu);
    asm("cvt.f32.f16 %0, %1;" : "=f"(f) : "h"(s));
    return f;
}
__device__ __forceinline__ float f16hi_f(uint32_t p) { return f16lo_f(p >> 16); }

__device__ __forceinline__ float sigmoidf_fast(float x) {
    return __fdividef(1.0f, 1.0f + __expf(-x));
}
__device__ __forceinline__ float tanhf_fast(float x) {
    return 1.0f - __fdividef(2.0f, __expf(2.0f * x) + 1.0f);
}

#define LDSM4(r0, r1, r2, r3, a)                                            \
    asm volatile("ldmatrix.sync.aligned.m8n8.x4.shared.b16 {%0,%1,%2,%3}, [%4];" \
                 : "=r"(r0), "=r"(r1), "=r"(r2), "=r"(r3) : "r"(a))

#define MMA16816(c, a0, a1, a2, a3, b0, b1)                                 \
    asm volatile("mma.sync.aligned.m16n8k16.row.col.f32.f16.f16.f32 "       \
                 "{%0,%1,%2,%3}, {%4,%5,%6,%7}, {%8,%9}, {%0,%1,%2,%3};"    \
                 : "+f"((c)[0]), "+f"((c)[1]), "+f"((c)[2]), "+f"((c)[3])   \
                 : "r"(a0), "r"(a1), "r"(a2), "r"(a3), "r"(b0), "r"(b1))

// ---------------------------------------------------------------------------
// zcnt (+ fused index-dtype detection in block 0)
// ---------------------------------------------------------------------------
__global__ void zcnt_kernel(const unsigned long long* __restrict__ src,
                            const unsigned long long* __restrict__ dst, int Nn) {
    int i = blockIdx.x * blockDim.x + threadIdx.x;
    if (i < Nn) g_cnt[i] = 0;
    if (i == 0) {
        unsigned long long acc = 0;
#pragma unroll
        for (int k = 0; k < 8; k++) acc |= (src[k] >> 32) | (dst[k] >> 32);
        g_is32 = (acc != 0ULL) ? 1 : 0;
    }
}

__global__ void hist_kernel(const void* __restrict__ dstp, int E) {
    int e = blockIdx.x * blockDim.x + threadIdx.x;
    if (e >= E) return;
    int d = g_is32 ? ((const int*)dstp)[e]
                   : (int)((const long long*)dstp)[e];
    atomicAdd(&g_cnt[d], 1);
}

// Hierarchical scan A: 1024-wide block scan; g_off = within-block exclusive.
__global__ void __launch_bounds__(1024) scanA_kernel(int Nn) {
    __shared__ int ws[32];
    const int t = threadIdx.x, lane = t & 31, wid = t >> 5;
    const int i = blockIdx.x * 1024 + t;
    int c = (i < Nn) ? g_cnt[i] : 0;
    int v = c;
#pragma unroll
    for (int d = 1; d < 32; d <<= 1) {
        int n = __shfl_up_sync(0xffffffffu, v, d);
        if (lane >= d) v += n;
    }
    if (lane == 31) ws[wid] = v;
    __syncthreads();
    if (wid == 0) {
        int wv = ws[lane];
#pragma unroll
        for (int d = 1; d < 32; d <<= 1) {
            int n = __shfl_up_sync(0xffffffffu, wv, d);
            if (lane >= d) wv += n;
        }
        ws[lane] = wv;
    }
    __syncthreads();
    int incl = v + (wid ? ws[wid - 1] : 0);
    if (i < Nn) g_off[i] = incl - c;
    if (t == 1023) g_blk[blockIdx.x] = incl;
}

// scanC with block-offset reduction folded in (each block redundantly sums
// the preceding 1024-block totals itself; <=127 adds).
__global__ void __launch_bounds__(256) scanC_kernel(int Nn, int E) {
    __shared__ int ssum[8];
    const int t = threadIdx.x, lane = t & 31, wid = t >> 5;
    const int myblk = blockIdx.x >> 2;
    int v = (t < 128 && t < myblk) ? g_blk[t] : 0;
#pragma unroll
    for (int d = 16; d > 0; d >>= 1) v += __shfl_down_sync(0xffffffffu, v, d);
    if (lane == 0) ssum[wid] = v;
    __syncthreads();
    int blkoff = ssum[0] + ssum[1] + ssum[2] + ssum[3];

    int i = blockIdx.x * 256 + t;
    if (i < Nn) {
        int off = g_off[i] + blkoff;
        g_off[i] = off;
        g_cnt[i] = off;
    }
    if (i == 0) g_off[Nn] = E;
}

__global__ void reorder_kernel(const void* __restrict__ srcp,
                               const void* __restrict__ dstp,
                               const float* __restrict__ ew, int E) {
    int e = blockIdx.x * blockDim.x + threadIdx.x;
    if (e >= E) return;
    int s, d;
    if (g_is32) {
        s = ((const int*)srcp)[e];
        d = ((const int*)dstp)[e];
    } else {
        s = (int)((const long long*)srcp)[e];
        d = (int)((const long long*)dstp)[e];
    }
    int pos = atomicAdd(&g_cnt[d], 1);
    g_rec[pos] = make_uint2((uint32_t)s, __float_as_uint(__ldg(&ew[e])));
}

// ---------------------------------------------------------------------------
// Accumulate: half-warp per node, lane owns a float4 part; unroll-4 for MLP.
// ---------------------------------------------------------------------------
__global__ void __launch_bounds__(256) accum_kernel(const float4* __restrict__ h4,
                                                    int Nn) {
    int gid = blockIdx.x * blockDim.x + threadIdx.x;
    int node = gid >> 4, p = gid & 15;
    if (node >= Nn) return;
    int e = g_off[node];
    const int end = g_off[node + 1];
    float4 acc = make_float4(0.f, 0.f, 0.f, 0.f);

    for (; e + 4 <= end; e += 4) {
        uint2 r0 = g_rec[e],     r1 = g_rec[e + 1];
        uint2 r2 = g_rec[e + 2], r3 = g_rec[e + 3];
        float4 v0 = __ldg(&h4[(size_t)r0.x * 16 + p]);
        float4 v1 = __ldg(&h4[(size_t)r1.x * 16 + p]);
        float4 v2 = __ldg(&h4[(size_t)r2.x * 16 + p]);
        float4 v3 = __ldg(&h4[(size_t)r3.x * 16 + p]);
        float w0 = __uint_as_float(r0.y), w1 = __uint_as_float(r1.y);
        float w2 = __uint_as_float(r2.y), w3 = __uint_as_float(r3.y);
        acc.x = fmaf(v0.x, w0, acc.x); acc.y = fmaf(v0.y, w0, acc.y);
        acc.z = fmaf(v0.z, w0, acc.z); acc.w = fmaf(v0.w, w0, acc.w);
        acc.x = fmaf(v1.x, w1, acc.x); acc.y = fmaf(v1.y, w1, acc.y);
        acc.z = fmaf(v1.z, w1, acc.z); acc.w = fmaf(v1.w, w1, acc.w);
        acc.x = fmaf(v2.x, w2, acc.x); acc.y = fmaf(v2.y, w2, acc.y);
        acc.z = fmaf(v2.z, w2, acc.z); acc.w = fmaf(v2.w, w2, acc.w);
        acc.x = fmaf(v3.x, w3, acc.x); acc.y = fmaf(v3.y, w3, acc.y);
        acc.z = fmaf(v3.z, w3, acc.z); acc.w = fmaf(v3.w, w3, acc.w);
    }
    for (; e < end; e++) {
        uint2 r = g_rec[e];
        float4 v = __ldg(&h4[(size_t)r.x * 16 + p]);
        float w = __uint_as_float(r.y);
        acc.x = fmaf(v.x, w, acc.x); acc.y = fmaf(v.y, w, acc.y);
        acc.z = fmaf(v.z, w, acc.z); acc.w = fmaf(v.w, w, acc.w);
    }
    g_hnew4[node * 16 + p] = acc;
}

// ---------------------------------------------------------------------------
// prep — fp16 weight image, GROUPED col order [r|z|i_n|h_n], + biases.
// ---------------------------------------------------------------------------
__global__ void prep_kernel(const float* __restrict__ Wih,
                            const float* __restrict__ Whh,
                            const float* __restrict__ bih,
                            const float* __restrict__ bhh) {
    int idx = blockIdx.x * blockDim.x + threadIdx.x;   // 256 cols' x 32 quads
    if (idx < 8192) {
        int colp = idx >> 5, q = idx & 31;
        int g = colp >> 6, j = colp & 63;
        int kk = (q & 15) * 4;
        bool isX = (q < 16);
        float4 v = make_float4(0.f, 0.f, 0.f, 0.f);
        const float* srcRow = nullptr;
        if (g == 0)      srcRow = isX ? &Wih[j * 64]         : &Whh[j * 64];
        else if (g == 1) srcRow = isX ? &Wih[(64 + j) * 64]  : &Whh[(64 + j) * 64];
        else if (g == 2) srcRow = isX ? &Wih[(128 + j) * 64] : nullptr;
        else             srcRow = isX ? nullptr              : &Whh[(128 + j) * 64];
        if (srcRow) v = *(const float4*)(srcRow + kk);

        uint32_t h01 = cvth2(v.y, v.x), h23 = cvth2(v.w, v.z);
        uint32_t off = (uint32_t)colp * STRIDE_A + ((q >> 1) << 4) + ((q & 1) << 3);
        *(uint2*)(g_Bimg + off) = make_uint2(h01, h23);
    }
    if (idx < 64) {
        g_biasf[idx]       = bih[idx] + bhh[idx];
        g_biasf[64 + idx]  = bih[64 + idx] + bhh[64 + idx];
        g_biasf[128 + idx] = bih[128 + idx];
        g_biasf[192 + idx] = bhh[128 + idx];
    }
}

// ---------------------------------------------------------------------------
// GEMM + GRU epilogue: warp-independent 16-row tiles; grouped-gate layout;
// fp16 2-pass split: A = Ahi + Alo (fp16), B single fp16. One B LDSM serves
// 4 MMAs. Gate sparsity: i_n only k-steps 0..3, h_n only 4..7.
// ---------------------------------------------------------------------------
#define GEMM_STEP(S, NB)                                                       \
    do {                                                                       \
        uint32_t b0, b1, b2, b3;                                               \
        LDSM4(b0, b1, b2, b3,                                                  \
              b_base + (uint32_t)(NB) * (16 * STRIDE_A) + (uint32_t)(S) * 32); \
        float* c0 = &acc[((NB) * 2) * 4];                                      \
        float* c1 = &acc[((NB) * 2 + 1) * 4];                                  \
        MMA16816(c0, ah0, ah1, ah2, ah3, b0, b1);                              \
        MMA16816(c1, ah0, ah1, ah2, ah3, b2, b3);                              \
        MMA16816(c0, al0, al1, al2, al3, b0, b1);                              \
        MMA16816(c1, al0, al1, al2, al3, b2, b3);                              \
    } while (0)

__global__ void __launch_bounds__(256, 1)
gemm_gru_kernel(const float4* __restrict__ h4, float* __restrict__ out,
                int Nn, int n_tiles16) {
    extern __shared__ __align__(16) char smem[];
    const uint32_t sb = smem_u32(smem);
    const int tid = threadIdx.x;
    const int w = tid >> 5, l = tid & 31;
    const int r0q = l >> 2, tg = l & 3;

    // --- B image + bias -> SMEM ---
    {
        const uint4* srcB = (const uint4*)g_Bimg;
        uint4* dstB = (uint4*)(smem + SM_B);
        for (int i = tid; i < B_IMG / 16; i += 256) dstB[i] = srcB[i];
        ((float*)smem)[tid] = g_biasf[tid];
    }
    __syncthreads();

    const int warpA_off = SM_A + w * A_WARP;
    const int sel = l >> 3;
    const uint32_t a_base = sb + (uint32_t)warpA_off +
        (uint32_t)((((sel & 1) << 3) + (l & 7)) * STRIDE_A + ((sel >> 1) << 4));
    const uint32_t b_base = sb + SM_B +
        (uint32_t)((((sel >> 1) << 3) + (l & 7)) * STRIDE_A + ((sel & 1) << 4));

    for (int tw = blockIdx.x * 8 + w; tw < n_tiles16; tw += gridDim.x * 8) {
        const int m0 = tw << 4;

        // --- A tile (16 rows, warp-private): f32 -> fp16 hi/lo split ---
#pragma unroll
        for (int it = 0; it < 16; it++) {
            int node = m0 + it;
            int kq = l;                               // 4-k quad; <16: hnew, >=16: h
            float4 v = make_float4(0.f, 0.f, 0.f, 0.f);
            if (node < Nn)
                v = (kq < 16) ? g_hnew4[node * 16 + kq]
                              : __ldg(&h4[node * 16 + (kq - 16)]);
            uint32_t h01 = cvth2(v.y, v.x), h23 = cvth2(v.w, v.z);
            uint32_t l01 = cvth2(v.y - f16hi_f(h01), v.x - f16lo_f(h01));
            uint32_t l23 = cvth2(v.w - f16hi_f(h23), v.z - f16lo_f(h23));
            uint32_t off = (uint32_t)warpA_off + (uint32_t)it * STRIDE_A +
                           ((uint32_t)(kq >> 1) << 4) + ((uint32_t)(kq & 1) << 3);
            *(uint2*)(smem + off)            = make_uint2(h01, h23);
            *(uint2*)(smem + off + A_HALF_W) = make_uint2(l01, l23);
        }
        __syncwarp();

        float acc[128];
#pragma unroll
        for (int i = 0; i < 128; i++) acc[i] = 0.f;

        // ---- fp16 2-pass: (Ahi + Alo) x B, sparsity-aware n-blocks ----
#pragma unroll 1
        for (int s = 0; s < 4; s++) {          // low-k: r,z + i_n (nb 0..11)
            uint32_t ah0, ah1, ah2, ah3, al0, al1, al2, al3;
            LDSM4(ah0, ah1, ah2, ah3, a_base + (uint32_t)s * 32);
            LDSM4(al0, al1, al2, al3, a_base + A_HALF_W + (uint32_t)s * 32);
#pragma unroll
            for (int q = 0; q < 12; q++) GEMM_STEP(s, q);
        }
#pragma unroll 1
        for (int s = 4; s < 8; s++) {          // high-k: r,z + h_n (nb 12..15)
            uint32_t ah0, ah1, ah2, ah3, al0, al1, al2, al3;
            LDSM4(ah0, ah1, ah2, ah3, a_base + (uint32_t)s * 32);
            LDSM4(al0, al1, al2, al3, a_base + A_HALF_W + (uint32_t)s * 32);
#pragma unroll
            for (int q = 0; q < 12; q++) { int nb = (q < 8) ? q : q + 4; GEMM_STEP(s, nb); }
        }

        // --- Epilogue phase 1: gate math (no shuffles) ---
#pragma unroll
        for (int rs = 0; rs < 2; rs++) {
            const int node_local = r0q + rs * 8;
#pragma unroll
            for (int fn = 0; fn < 8; fn++) {
                const uint32_t bj = (uint32_t)((fn * 8 + tg * 2) * 4);
                float2 br = *(const float2*)(smem + SM_BIAS + bj);
                float2 bz = *(const float2*)(smem + SM_BIAS + 256 + bj);
                float2 bi = *(const float2*)(smem + SM_BIAS + 512 + bj);
                float2 bh = *(const float2*)(smem + SM_BIAS + 768 + bj);
#pragma unroll
                for (int b = 0; b < 2; b++) {
                    int j = fn * 8 + tg * 2 + b;
                    float rp = acc[fn * 4 + 2 * rs + b];
                    float zp = acc[(fn + 8) * 4 + 2 * rs + b];
                    float ip = acc[(fn + 16) * 4 + 2 * rs + b];
                    float hp = acc[(fn + 24) * 4 + 2 * rs + b];
                    float rr = sigmoidf_fast(rp + (b ? br.y : br.x));
                    float zz = sigmoidf_fast(zp + (b ? bz.y : bz.x));
                    float nn = tanhf_fast(ip + (b ? bi.y : bi.x) +
                                          rr * (hp + (b ? bh.y : bh.x)));
                    int kcol = 64 + j;
                    uint32_t hoff = (uint32_t)warpA_off +
                                    (uint32_t)node_local * STRIDE_A +
                                    ((uint32_t)(kcol >> 3) << 4) +
                                    ((uint32_t)(kcol & 7) << 1);
                    uint32_t hib = *(const unsigned short*)(smem + hoff);
                    uint32_t lob = *(const unsigned short*)(smem + hoff + A_HALF_W);
                    float hv = f16lo_f(hib) + f16lo_f(lob);
                    acc[fn * 4 + 2 * rs + b] = (1.f - zz) * nn + zz * hv;
                }
            }
        }
        __syncwarp();

        // --- Epilogue phase 2: stage float2 into warp-private SMEM (XOR sw) ---
#pragma unroll
        for (int rs = 0; rs < 2; rs++) {
            const int nl = r0q + rs * 8;
            const uint32_t sw = ((uint32_t)(nl & 7)) << 2;
#pragma unroll
            for (int fn = 0; fn < 8; fn++) {
                uint32_t u = (uint32_t)(fn * 4 + tg);
                uint32_t sa = (uint32_t)warpA_off + (uint32_t)nl * 256 +
                              ((u ^ sw) << 3);
                *(float2*)(smem + sa) =
                    make_float2(acc[fn * 4 + 2 * rs], acc[fn * 4 + 2 * rs + 1]);
            }
        }
        __syncwarp();

        // --- Epilogue phase 3: coalesced 16B stores ---
#pragma unroll
        for (int it = 0; it < 8; it++) {
            int idx = it * 32 + l;
            int nl = idx >> 4, c16 = idx & 15;
            uint32_t ra = (uint32_t)warpA_off + (uint32_t)nl * 256 +
                          ((uint32_t)(c16 ^ ((nl & 7) << 1)) << 4);
            float4 v = *(const float4*)(smem + ra);
            int node = m0 + nl;
            if (node < Nn) *(float4*)(out + (size_t)node * 64 + c16 * 4) = v;
        }
        __syncwarp();
    }
}

// ---------------------------------------------------------------------------
// Launch
// ---------------------------------------------------------------------------
extern "C" void kernel_launch(void* const* d_in, const int* in_sizes, int n_in,
                              void* d_out, int out_size) {
    const float* h   = (const float*)d_in[0];
    const float* ew  = (const float*)d_in[1];
    const float* Wih = (const float*)d_in[2];
    const float* Whh = (const float*)d_in[3];
    const float* bih = (const float*)d_in[4];
    const float* bhh = (const float*)d_in[5];
    const void* srcp = d_in[6];
    const void* dstp = d_in[7];
    float* out       = (float*)d_out;

    int E  = in_sizes[1];
    int Nn = in_sizes[0] / D;
    int n_tiles16 = (Nn + 15) / 16;
    int eblocks = (E + 255) / 256;
    int nb = (Nn + 1023) / 1024;

    zcnt_kernel<<<(Nn + 255) / 256, 256>>>((const unsigned long long*)srcp,
                                           (const unsigned long long*)dstp, Nn);
    hist_kernel<<<eblocks, 256>>>(dstp, E);
    scanA_kernel<<<nb, 1024>>>(Nn);
    scanC_kernel<<<(Nn + 255) / 256, 256>>>(Nn, E);
    reorder_kernel<<<eblocks, 256>>>(srcp, dstp, ew, E);

    prep_kernel<<<32, 256>>>(Wih, Whh, bih, bhh);

    accum_kernel<<<(Nn * 16 + 255) / 256, 256>>>((const float4*)h, Nn);

    cudaFuncSetAttribute(gemm_gru_kernel,
                         cudaFuncAttributeMaxDynamicSharedMemorySize, SM_TOT);
    gemm_gru_kernel<<<148, 256, SM_TOT>>>((const float4*)h, out, Nn, n_tiles16);
}

// round 13
// speedup vs baseline: 1.7288x; 1.1607x over previous
#include <cuda_runtime.h>
#include <cuda_fp16.h>
#include <cstdint>

#define D 64
#define NMAX 100000
#define EMAX 1664000

// ---------------------------------------------------------------------------
// Device scratch
// ---------------------------------------------------------------------------
__device__ float4  g_hnew4[NMAX * (D / 4)];   // h_new result (25.6 MB)
__device__ uint2   g_rec[EMAX];               // CSR records: (src, w bits)
__device__ int     g_cnt[NMAX];               // histogram / write cursors
__device__ int     g_off[NMAX + 1];           // CSR row offsets
__device__ int     g_blk[128];                // block totals for scan
__device__ uint8_t g_Bimg[69632];             // fp16 weight image (grouped cols)
__device__ float   g_biasf[256];              // biases: [r(64)|z(64)|i_n(64)|h_n(64)]
__device__ int     g_is32;                    // src/dst dtype flag

// SMEM map for the GEMM kernel (per-PAIR A regions now)
#define STRIDE_A 272            // 128 k * 2B padded to 17*16B (ldmatrix conflict-free)
#define A_HALF_W 4352           // per-pair A half: 16 rows * 272
#define A_WARP   8704           // per-pair A region (hi + lo)
#define B_IMG    69632          // 256 rows * 272 (single fp16 image)
#define SM_BIAS  0
#define SM_A     1024
#define SM_B     (SM_A + 8 * A_WARP)          // 70656
#define SM_TOT   (SM_B + B_IMG)               // 140288

// ---------------------------------------------------------------------------
// Helpers
// ---------------------------------------------------------------------------
__device__ __forceinline__ uint32_t smem_u32(const void* p) {
    uint32_t a;
    asm("{ .reg .u64 t; cvta.to.shared.u64 t, %1; cvt.u32.u64 %0, t; }"
        : "=r"(a) : "l"(p));
    return a;
}
__device__ __forceinline__ uint32_t cvth2(float hi, float lo) {
    uint32_t d;
    asm("cvt.rn.f16x2.f32 %0, %1, %2;" : "=r"(d) : "f"(hi), "f"(lo));
    return d;
}
__device__ __forceinline__ float f16lo_f(uint32_t p) {
    float f; unsigned short s = (unsigned short)(p & 0xffffu);
    asm("cvt.f32.f16 %0, %1;" : "=f"(f) : "h"(s));
    return f;
}
__device__ __forceinline__ float f16hi_f(uint32_t p) { return f16lo_f(p >> 16); }

__device__ __forceinline__ float sigmoidf_fast(float x) {
    return __fdividef(1.0f, 1.0f + __expf(-x));
}
__device__ __forceinline__ float tanhf_fast(float x) {
    return 1.0f - __fdividef(2.0f, __expf(2.0f * x) + 1.0f);
}

#define LDSM4(r0, r1, r2, r3, a)                                            \
    asm volatile("ldmatrix.sync.aligned.m8n8.x4.shared.b16 {%0,%1,%2,%3}, [%4];" \
                 : "=r"(r0), "=r"(r1), "=r"(r2), "=r"(r3) : "r"(a))

#define MMA16816(c, a0, a1, a2, a3, b0, b1)                                 \
    asm volatile("mma.sync.aligned.m16n8k16.row.col.f32.f16.f16.f32 "       \
                 "{%0,%1,%2,%3}, {%4,%5,%6,%7}, {%8,%9}, {%0,%1,%2,%3};"    \
                 : "+f"((c)[0]), "+f"((c)[1]), "+f"((c)[2]), "+f"((c)[3])   \
                 : "r"(a0), "r"(a1), "r"(a2), "r"(a3), "r"(b0), "r"(b1))

#define PAIR_BAR(id) asm volatile("bar.sync %0, 64;" :: "r"(id) : "memory")

// ---------------------------------------------------------------------------
// zcnt (+ fused index-dtype detection in block 0)
// ---------------------------------------------------------------------------
__global__ void zcnt_kernel(const unsigned long long* __restrict__ src,
                            const unsigned long long* __restrict__ dst, int Nn) {
    int i = blockIdx.x * blockDim.x + threadIdx.x;
    if (i < Nn) g_cnt[i] = 0;
    if (i == 0) {
        unsigned long long acc = 0;
#pragma unroll
        for (int k = 0; k < 8; k++) acc |= (src[k] >> 32) | (dst[k] >> 32);
        g_is32 = (acc != 0ULL) ? 1 : 0;
    }
}

__global__ void hist_kernel(const void* __restrict__ dstp, int E) {
    int e = blockIdx.x * blockDim.x + threadIdx.x;
    if (e >= E) return;
    int d = g_is32 ? ((const int*)dstp)[e]
                   : (int)((const long long*)dstp)[e];
    atomicAdd(&g_cnt[d], 1);
}

// Hierarchical scan A: 1024-wide block scan; g_off = within-block exclusive.
__global__ void __launch_bounds__(1024) scanA_kernel(int Nn) {
    __shared__ int ws[32];
    const int t = threadIdx.x, lane = t & 31, wid = t >> 5;
    const int i = blockIdx.x * 1024 + t;
    int c = (i < Nn) ? g_cnt[i] : 0;
    int v = c;
#pragma unroll
    for (int d = 1; d < 32; d <<= 1) {
        int n = __shfl_up_sync(0xffffffffu, v, d);
        if (lane >= d) v += n;
    }
    if (lane == 31) ws[wid] = v;
    __syncthreads();
    if (wid == 0) {
        int wv = ws[lane];
#pragma unroll
        for (int d = 1; d < 32; d <<= 1) {
            int n = __shfl_up_sync(0xffffffffu, wv, d);
            if (lane >= d) wv += n;
        }
        ws[lane] = wv;
    }
    __syncthreads();
    int incl = v + (wid ? ws[wid - 1] : 0);
    if (i < Nn) g_off[i] = incl - c;
    if (t == 1023) g_blk[blockIdx.x] = incl;
}

// scanC with block-offset reduction folded in.
__global__ void __launch_bounds__(256) scanC_kernel(int Nn, int E) {
    __shared__ int ssum[8];
    const int t = threadIdx.x, lane = t & 31, wid = t >> 5;
    const int myblk = blockIdx.x >> 2;
    int v = (t < 128 && t < myblk) ? g_blk[t] : 0;
#pragma unroll
    for (int d = 16; d > 0; d >>= 1) v += __shfl_down_sync(0xffffffffu, v, d);
    if (lane == 0) ssum[wid] = v;
    __syncthreads();
    int blkoff = ssum[0] + ssum[1] + ssum[2] + ssum[3];

    int i = blockIdx.x * 256 + t;
    if (i < Nn) {
        int off = g_off[i] + blkoff;
        g_off[i] = off;
        g_cnt[i] = off;
    }
    if (i == 0) g_off[Nn] = E;
}

__global__ void reorder_kernel(const void* __restrict__ srcp,
                               const void* __restrict__ dstp,
                               const float* __restrict__ ew, int E) {
    int e = blockIdx.x * blockDim.x + threadIdx.x;
    if (e >= E) return;
    int s, d;
    if (g_is32) {
        s = ((const int*)srcp)[e];
        d = ((const int*)dstp)[e];
    } else {
        s = (int)((const long long*)srcp)[e];
        d = (int)((const long long*)dstp)[e];
    }
    int pos = atomicAdd(&g_cnt[d], 1);
    g_rec[pos] = make_uint2((uint32_t)s, __float_as_uint(__ldg(&ew[e])));
}

// ---------------------------------------------------------------------------
// Accumulate: half-warp per node, lane owns a float4 part; unroll-4 for MLP.
// ---------------------------------------------------------------------------
__global__ void __launch_bounds__(256) accum_kernel(const float4* __restrict__ h4,
                                                    int Nn) {
    int gid = blockIdx.x * blockDim.x + threadIdx.x;
    int node = gid >> 4, p = gid & 15;
    if (node >= Nn) return;
    int e = g_off[node];
    const int end = g_off[node + 1];
    float4 acc = make_float4(0.f, 0.f, 0.f, 0.f);

    for (; e + 4 <= end; e += 4) {
        uint2 r0 = g_rec[e],     r1 = g_rec[e + 1];
        uint2 r2 = g_rec[e + 2], r3 = g_rec[e + 3];
        float4 v0 = __ldg(&h4[(size_t)r0.x * 16 + p]);
        float4 v1 = __ldg(&h4[(size_t)r1.x * 16 + p]);
        float4 v2 = __ldg(&h4[(size_t)r2.x * 16 + p]);
        float4 v3 = __ldg(&h4[(size_t)r3.x * 16 + p]);
        float w0 = __uint_as_float(r0.y), w1 = __uint_as_float(r1.y);
        float w2 = __uint_as_float(r2.y), w3 = __uint_as_float(r3.y);
        acc.x = fmaf(v0.x, w0, acc.x); acc.y = fmaf(v0.y, w0, acc.y);
        acc.z = fmaf(v0.z, w0, acc.z); acc.w = fmaf(v0.w, w0, acc.w);
        acc.x = fmaf(v1.x, w1, acc.x); acc.y = fmaf(v1.y, w1, acc.y);
        acc.z = fmaf(v1.z, w1, acc.z); acc.w = fmaf(v1.w, w1, acc.w);
        acc.x = fmaf(v2.x, w2, acc.x); acc.y = fmaf(v2.y, w2, acc.y);
        acc.z = fmaf(v2.z, w2, acc.z); acc.w = fmaf(v2.w, w2, acc.w);
        acc.x = fmaf(v3.x, w3, acc.x); acc.y = fmaf(v3.y, w3, acc.y);
        acc.z = fmaf(v3.z, w3, acc.z); acc.w = fmaf(v3.w, w3, acc.w);
    }
    for (; e < end; e++) {
        uint2 r = g_rec[e];
        float4 v = __ldg(&h4[(size_t)r.x * 16 + p]);
        float w = __uint_as_float(r.y);
        acc.x = fmaf(v.x, w, acc.x); acc.y = fmaf(v.y, w, acc.y);
        acc.z = fmaf(v.z, w, acc.z); acc.w = fmaf(v.w, w, acc.w);
    }
    g_hnew4[node * 16 + p] = acc;
}

// ---------------------------------------------------------------------------
// prep — fp16 weight image, GROUPED col order [r|z|i_n|h_n], + biases.
// ---------------------------------------------------------------------------
__global__ void prep_kernel(const float* __restrict__ Wih,
                            const float* __restrict__ Whh,
                            const float* __restrict__ bih,
                            const float* __restrict__ bhh) {
    int idx = blockIdx.x * blockDim.x + threadIdx.x;
    if (idx < 8192) {
        int colp = idx >> 5, q = idx & 31;
        int g = colp >> 6, j = colp & 63;
        int kk = (q & 15) * 4;
        bool isX = (q < 16);
        float4 v = make_float4(0.f, 0.f, 0.f, 0.f);
        const float* srcRow = nullptr;
        if (g == 0)      srcRow = isX ? &Wih[j * 64]         : &Whh[j * 64];
        else if (g == 1) srcRow = isX ? &Wih[(64 + j) * 64]  : &Whh[(64 + j) * 64];
        else if (g == 2) srcRow = isX ? &Wih[(128 + j) * 64] : nullptr;
        else             srcRow = isX ? nullptr              : &Whh[(128 + j) * 64];
        if (srcRow) v = *(const float4*)(srcRow + kk);

        uint32_t h01 = cvth2(v.y, v.x), h23 = cvth2(v.w, v.z);
        uint32_t off = (uint32_t)colp * STRIDE_A + ((q >> 1) << 4) + ((q & 1) << 3);
        *(uint2*)(g_Bimg + off) = make_uint2(h01, h23);
    }
    if (idx < 64) {
        g_biasf[idx]       = bih[idx] + bhh[idx];
        g_biasf[64 + idx]  = bih[64 + idx] + bhh[64 + idx];
        g_biasf[128 + idx] = bih[128 + idx];
        g_biasf[192 + idx] = bhh[128 + idx];
    }
}

// ---------------------------------------------------------------------------
// GEMM + GRU epilogue: 512 threads (16 warps = 8 PAIRS) per CTA.
// Pair shares one 16-row A tile; each warp owns alternating 16-col granules
// (parity), so each warp has complete r/z/i_n/h_n quadruples for its j's.
// 64 accumulators/thread -> <=128 regs -> 4 warps/SMSP (2x latency hiding).
// ---------------------------------------------------------------------------
__global__ void __launch_bounds__(512, 1)
gemm_gru_kernel(const float4* __restrict__ h4, float* __restrict__ out,
                int Nn, int n_tiles16) {
    extern __shared__ __align__(16) char smem[];
    const uint32_t sb = smem_u32(smem);
    const int tid = threadIdx.x;
    const int w = tid >> 5, l = tid & 31;
    const int pair = w >> 1, par = w & 1;
    const int t2 = tid & 63;                 // thread-in-pair
    const int r0q = l >> 2, tg = l & 3;
    const int barid = pair + 1;

    // --- B image + bias -> SMEM ---
    {
        const uint4* srcB = (const uint4*)g_Bimg;
        uint4* dstB = (uint4*)(smem + SM_B);
        for (int i = tid; i < B_IMG / 16; i += 512) dstB[i] = srcB[i];
        if (tid < 256) ((float*)smem)[tid] = g_biasf[tid];
    }
    __syncthreads();

    const int pairA_off = SM_A + pair * A_WARP;
    const int sel = l >> 3;
    const uint32_t a_base = sb + (uint32_t)pairA_off +
        (uint32_t)((((sel & 1) << 3) + (l & 7)) * STRIDE_A + ((sel >> 1) << 4));
    // warp's B base: granule nb = 2m + par
    const uint32_t b_base = sb + SM_B + (uint32_t)par * (16 * STRIDE_A) +
        (uint32_t)((((sel >> 1) << 3) + (l & 7)) * STRIDE_A + ((sel & 1) << 4));

    for (int tw = blockIdx.x * 8 + pair; tw < n_tiles16; tw += gridDim.x * 8) {
        const int m0 = tw << 4;

        // --- A tile (16 rows, pair-shared): f32 -> fp16 hi/lo split ---
        // 64 threads x 8 iters: row = ii*2 + (t2>>5), kq = t2&31
#pragma unroll
        for (int ii = 0; ii < 8; ii++) {
            int row = ii * 2 + (t2 >> 5);
            int node = m0 + row;
            int kq = t2 & 31;                         // <16: hnew, >=16: h
            float4 v = make_float4(0.f, 0.f, 0.f, 0.f);
            if (node < Nn)
                v = (kq < 16) ? g_hnew4[node * 16 + kq]
                              : __ldg(&h4[node * 16 + (kq - 16)]);
            uint32_t h01 = cvth2(v.y, v.x), h23 = cvth2(v.w, v.z);
            uint32_t l01 = cvth2(v.y - f16hi_f(h01), v.x - f16lo_f(h01));
            uint32_t l23 = cvth2(v.w - f16hi_f(h23), v.z - f16lo_f(h23));
            uint32_t off = (uint32_t)pairA_off + (uint32_t)row * STRIDE_A +
                           ((uint32_t)(kq >> 1) << 4) + ((uint32_t)(kq & 1) << 3);
            *(uint2*)(smem + off)            = make_uint2(h01, h23);
            *(uint2*)(smem + off + A_HALF_W) = make_uint2(l01, l23);
        }
        PAIR_BAR(barid);          // A tile complete for both warps

        float acc[64];
#pragma unroll
        for (int i = 0; i < 64; i++) acc[i] = 0.f;

        // ---- fp16 2-pass GEMM, warp granules nb = 2m+par ----
        // m: 0,1=r  2,3=z  4,5=i_n(k<64 only)  6,7=h_n(k>=64 only)
#pragma unroll 1
        for (int s = 0; s < 4; s++) {
            uint32_t ah0, ah1, ah2, ah3, al0, al1, al2, al3;
            LDSM4(ah0, ah1, ah2, ah3, a_base + (uint32_t)s * 32);
            LDSM4(al0, al1, al2, al3, a_base + A_HALF_W + (uint32_t)s * 32);
#pragma unroll
            for (int m = 0; m < 6; m++) {
                uint32_t b0, b1, b2, b3;
                LDSM4(b0, b1, b2, b3,
                      b_base + (uint32_t)m * (32 * STRIDE_A) + (uint32_t)s * 32);
                float* c0 = &acc[m * 8];
                float* c1 = &acc[m * 8 + 4];
                MMA16816(c0, ah0, ah1, ah2, ah3, b0, b1);
                MMA16816(c1, ah0, ah1, ah2, ah3, b2, b3);
                MMA16816(c0, al0, al1, al2, al3, b0, b1);
                MMA16816(c1, al0, al1, al2, al3, b2, b3);
            }
        }
#pragma unroll 1
        for (int s = 4; s < 8; s++) {
            uint32_t ah0, ah1, ah2, ah3, al0, al1, al2, al3;
            LDSM4(ah0, ah1, ah2, ah3, a_base + (uint32_t)s * 32);
            LDSM4(al0, al1, al2, al3, a_base + A_HALF_W + (uint32_t)s * 32);
#pragma unroll
            for (int q = 0; q < 6; q++) {
                int m = (q < 4) ? q : q + 2;          // {0,1,2,3,6,7}
                uint32_t b0, b1, b2, b3;
                LDSM4(b0, b1, b2, b3,
                      b_base + (uint32_t)m * (32 * STRIDE_A) + (uint32_t)s * 32);
                float* c0 = &acc[m * 8];
                float* c1 = &acc[m * 8 + 4];
                MMA16816(c0, ah0, ah1, ah2, ah3, b0, b1);
                MMA16816(c1, ah0, ah1, ah2, ah3, b2, b3);
                MMA16816(c0, al0, al1, al2, al3, b0, b1);
                MMA16816(c1, al0, al1, al2, al3, b2, b3);
            }
        }

        // --- Epilogue phase 1: gate math; j = 32u + 16par + 8f + 2tg + b ---
#pragma unroll
        for (int u = 0; u < 2; u++) {
#pragma unroll
            for (int f = 0; f < 2; f++) {
                const int jbase = 32 * u + 16 * par + 8 * f + 2 * tg;
                float2 br = *(const float2*)(smem + SM_BIAS + jbase * 4);
                float2 bz = *(const float2*)(smem + SM_BIAS + 256 + jbase * 4);
                float2 bi = *(const float2*)(smem + SM_BIAS + 512 + jbase * 4);
                float2 bh = *(const float2*)(smem + SM_BIAS + 768 + jbase * 4);
#pragma unroll
                for (int rs = 0; rs < 2; rs++) {
                    const int node_local = r0q + rs * 8;
#pragma unroll
                    for (int b = 0; b < 2; b++) {
                        int j = jbase + b;
                        int ai = f * 4 + 2 * rs + b;
                        float rp = acc[u * 8 + ai];
                        float zp = acc[(2 + u) * 8 + ai];
                        float ip = acc[(4 + u) * 8 + ai];
                        float hp = acc[(6 + u) * 8 + ai];
                        float rr = sigmoidf_fast(rp + (b ? br.y : br.x));
                        float zz = sigmoidf_fast(zp + (b ? bz.y : bz.x));
                        float nn = tanhf_fast(ip + (b ? bi.y : bi.x) +
                                              rr * (hp + (b ? bh.y : bh.x)));
                        int kcol = 64 + j;
                        uint32_t hoff = (uint32_t)pairA_off +
                                        (uint32_t)node_local * STRIDE_A +
                                        ((uint32_t)(kcol >> 3) << 4) +
                                        ((uint32_t)(kcol & 7) << 1);
                        uint32_t hib = *(const unsigned short*)(smem + hoff);
                        uint32_t lob = *(const unsigned short*)(smem + hoff + A_HALF_W);
                        float hv = f16lo_f(hib) + f16lo_f(lob);
                        acc[u * 8 + ai] = (1.f - zz) * nn + zz * hv;
                    }
                }
            }
        }
        PAIR_BAR(barid);          // all A reads done before staging overwrite

        // --- Phase 2: stage float2 into pair staging (XOR swizzle, 8B units) ---
#pragma unroll
        for (int u = 0; u < 2; u++) {
#pragma unroll
            for (int f = 0; f < 2; f++) {
#pragma unroll
                for (int rs = 0; rs < 2; rs++) {
                    const int row = r0q + rs * 8;
                    uint32_t u8 = (uint32_t)(16 * u + 8 * par + 4 * f + tg);
                    uint32_t sa = (uint32_t)pairA_off + (uint32_t)row * 256 +
                                  ((u8 ^ (((uint32_t)row & 7) << 2)) << 3);
                    *(float2*)(smem + sa) =
                        make_float2(acc[u * 8 + f * 4 + 2 * rs],
                                    acc[u * 8 + f * 4 + 2 * rs + 1]);
                }
            }
        }
        PAIR_BAR(barid);          // staging complete

        // --- Phase 3: coalesced 16B stores (64 threads x 4 iters) ---
#pragma unroll
        for (int it = 0; it < 4; it++) {
            int idx = it * 64 + t2;
            int nl = idx >> 4, c16 = idx & 15;
            uint32_t ra = (uint32_t)pairA_off + (uint32_t)nl * 256 +
                          ((((uint32_t)(2 * c16)) ^ (((uint32_t)nl & 7) << 2)) << 3);
            float4 v = *(const float4*)(smem + ra);
            int node = m0 + nl;
            if (node < Nn) *(float4*)(out + (size_t)node * 64 + c16 * 4) = v;
        }
        PAIR_BAR(barid);          // stores done before next tile's A-prep
    }
}

// ---------------------------------------------------------------------------
// Launch
// ---------------------------------------------------------------------------
extern "C" void kernel_launch(void* const* d_in, const int* in_sizes, int n_in,
                              void* d_out, int out_size) {
    const float* h   = (const float*)d_in[0];
    const float* ew  = (const float*)d_in[1];
    const float* Wih = (const float*)d_in[2];
    const float* Whh = (const float*)d_in[3];
    const float* bih = (const float*)d_in[4];
    const float* bhh = (const float*)d_in[5];
    const void* srcp = d_in[6];
    const void* dstp = d_in[7];
    float* out       = (float*)d_out;

    int E  = in_sizes[1];
    int Nn = in_sizes[0] / D;
    int n_tiles16 = (Nn + 15) / 16;
    int eblocks = (E + 255) / 256;
    int nb = (Nn + 1023) / 1024;

    zcnt_kernel<<<(Nn + 255) / 256, 256>>>((const unsigned long long*)srcp,
                                           (const unsigned long long*)dstp, Nn);
    hist_kernel<<<eblocks, 256>>>(dstp, E);
    scanA_kernel<<<nb, 1024>>>(Nn);
    scanC_kernel<<<(Nn + 255) / 256, 256>>>(Nn, E);
    reorder_kernel<<<eblocks, 256>>>(srcp, dstp, ew, E);

    prep_kernel<<<32, 256>>>(Wih, Whh, bih, bhh);

    accum_kernel<<<(Nn * 16 + 255) / 256, 256>>>((const float4*)h, Nn);

    cudaFuncSetAttribute(gemm_gru_kernel,
                         cudaFuncAttributeMaxDynamicSharedMemorySize, SM_TOT);
    gemm_gru_kernel<<<148, 512, SM_TOT>>>((const float4*)h, out, Nn, n_tiles16);
}

// round 14
// speedup vs baseline: 1.8592x; 1.0754x over previous
#include <cuda_runtime.h>
#include <cuda_fp16.h>
#include <cstdint>

#define D 64
#define NMAX 100000
#define EMAX 1664000

// ---------------------------------------------------------------------------
// Device scratch
// ---------------------------------------------------------------------------
__device__ float4  g_hnew4[NMAX * (D / 4)];   // h_new result (25.6 MB)
__device__ uint2   g_rec[EMAX];               // CSR records: (src, w bits)
__device__ int     g_cnt[NMAX];               // histogram / write cursors
__device__ int     g_off[NMAX + 1];           // CSR row offsets
__device__ int     g_blk[128];                // block totals for scan
__device__ uint8_t g_Bimg[69632];             // fp16 weight image (grouped cols)
__device__ float   g_biasf[256];              // biases: [r(64)|z(64)|i_n(64)|h_n(64)]
__device__ int     g_is32;                    // src/dst dtype flag

// SMEM map for the GEMM kernel (per-QUAD A regions; 6 quads / 768-thread CTA)
#define STRIDE_A 272            // 128 k * 2B padded to 17*16B (ldmatrix conflict-free)
#define A_HALF_W 4352           // per-quad A half: 16 rows * 272
#define A_WARP   8704           // per-quad A region (hi + lo)
#define N_QUAD   6
#define B_IMG    69632          // 256 rows * 272 (single fp16 image)
#define SM_BIAS  0
#define SM_A     1024
#define SM_B     (SM_A + N_QUAD * A_WARP)     // 53248
#define SM_TOT   (SM_B + B_IMG)               // 122880

// ---------------------------------------------------------------------------
// Helpers
// ---------------------------------------------------------------------------
__device__ __forceinline__ uint32_t smem_u32(const void* p) {
    uint32_t a;
    asm("{ .reg .u64 t; cvta.to.shared.u64 t, %1; cvt.u32.u64 %0, t; }"
        : "=r"(a) : "l"(p));
    return a;
}
__device__ __forceinline__ uint32_t cvth2(float hi, float lo) {
    uint32_t d;
    asm("cvt.rn.f16x2.f32 %0, %1, %2;" : "=r"(d) : "f"(hi), "f"(lo));
    return d;
}
__device__ __forceinline__ float f16lo_f(uint32_t p) {
    float f; unsigned short s = (unsigned short)(p & 0xffffu);
    asm("cvt.f32.f16 %0, %1;" : "=f"(f) : "h"(s));
    return f;
}
__device__ __forceinline__ float f16hi_f(uint32_t p) { return f16lo_f(p >> 16); }

__device__ __forceinline__ float sigmoidf_fast(float x) {
    return __fdividef(1.0f, 1.0f + __expf(-x));
}
__device__ __forceinline__ float tanhf_fast(float x) {
    return 1.0f - __fdividef(2.0f, __expf(2.0f * x) + 1.0f);
}

#define LDSM4(r0, r1, r2, r3, a)                                            \
    asm volatile("ldmatrix.sync.aligned.m8n8.x4.shared.b16 {%0,%1,%2,%3}, [%4];" \
                 : "=r"(r0), "=r"(r1), "=r"(r2), "=r"(r3) : "r"(a))

#define MMA16816(c, a0, a1, a2, a3, b0, b1)                                 \
    asm volatile("mma.sync.aligned.m16n8k16.row.col.f32.f16.f16.f32 "       \
                 "{%0,%1,%2,%3}, {%4,%5,%6,%7}, {%8,%9}, {%0,%1,%2,%3};"    \
                 : "+f"((c)[0]), "+f"((c)[1]), "+f"((c)[2]), "+f"((c)[3])   \
                 : "r"(a0), "r"(a1), "r"(a2), "r"(a3), "r"(b0), "r"(b1))

#define QUAD_BAR(id) asm volatile("bar.sync %0, 128;" :: "r"(id) : "memory")

// ---------------------------------------------------------------------------
// zcnt (+ fused index-dtype detection in block 0)
// ---------------------------------------------------------------------------
__global__ void zcnt_kernel(const unsigned long long* __restrict__ src,
                            const unsigned long long* __restrict__ dst, int Nn) {
    int i = blockIdx.x * blockDim.x + threadIdx.x;
    if (i < Nn) g_cnt[i] = 0;
    if (i == 0) {
        unsigned long long acc = 0;
#pragma unroll
        for (int k = 0; k < 8; k++) acc |= (src[k] >> 32) | (dst[k] >> 32);
        g_is32 = (acc != 0ULL) ? 1 : 0;
    }
}

__global__ void hist_kernel(const void* __restrict__ dstp, int E) {
    int e = blockIdx.x * blockDim.x + threadIdx.x;
    if (e >= E) return;
    int d = g_is32 ? ((const int*)dstp)[e]
                   : (int)((const long long*)dstp)[e];
    atomicAdd(&g_cnt[d], 1);
}

// Hierarchical scan A: 1024-wide block scan; g_off = within-block exclusive.
__global__ void __launch_bounds__(1024) scanA_kernel(int Nn) {
    __shared__ int ws[32];
    const int t = threadIdx.x, lane = t & 31, wid = t >> 5;
    const int i = blockIdx.x * 1024 + t;
    int c = (i < Nn) ? g_cnt[i] : 0;
    int v = c;
#pragma unroll
    for (int d = 1; d < 32; d <<= 1) {
        int n = __shfl_up_sync(0xffffffffu, v, d);
        if (lane >= d) v += n;
    }
    if (lane == 31) ws[wid] = v;
    __syncthreads();
    if (wid == 0) {
        int wv = ws[lane];
#pragma unroll
        for (int d = 1; d < 32; d <<= 1) {
            int n = __shfl_up_sync(0xffffffffu, wv, d);
            if (lane >= d) wv += n;
        }
        ws[lane] = wv;
    }
    __syncthreads();
    int incl = v + (wid ? ws[wid - 1] : 0);
    if (i < Nn) g_off[i] = incl - c;
    if (t == 1023) g_blk[blockIdx.x] = incl;
}

// scanC with block-offset reduction folded in.
__global__ void __launch_bounds__(256) scanC_kernel(int Nn, int E) {
    __shared__ int ssum[8];
    const int t = threadIdx.x, lane = t & 31, wid = t >> 5;
    const int myblk = blockIdx.x >> 2;
    int v = (t < 128 && t < myblk) ? g_blk[t] : 0;
#pragma unroll
    for (int d = 16; d > 0; d >>= 1) v += __shfl_down_sync(0xffffffffu, v, d);
    if (lane == 0) ssum[wid] = v;
    __syncthreads();
    int blkoff = ssum[0] + ssum[1] + ssum[2] + ssum[3];

    int i = blockIdx.x * 256 + t;
    if (i < Nn) {
        int off = g_off[i] + blkoff;
        g_off[i] = off;
        g_cnt[i] = off;
    }
    if (i == 0) g_off[Nn] = E;
}

__global__ void reorder_kernel(const void* __restrict__ srcp,
                               const void* __restrict__ dstp,
                               const float* __restrict__ ew, int E) {
    int e = blockIdx.x * blockDim.x + threadIdx.x;
    if (e >= E) return;
    int s, d;
    if (g_is32) {
        s = ((const int*)srcp)[e];
        d = ((const int*)dstp)[e];
    } else {
        s = (int)((const long long*)srcp)[e];
        d = (int)((const long long*)dstp)[e];
    }
    int pos = atomicAdd(&g_cnt[d], 1);
    g_rec[pos] = make_uint2((uint32_t)s, __float_as_uint(__ldg(&ew[e])));
}

// ---------------------------------------------------------------------------
// Accumulate: half-warp per node, lane owns a float4 part; unroll-4 for MLP.
// ---------------------------------------------------------------------------
__global__ void __launch_bounds__(256) accum_kernel(const float4* __restrict__ h4,
                                                    int Nn) {
    int gid = blockIdx.x * blockDim.x + threadIdx.x;
    int node = gid >> 4, p = gid & 15;
    if (node >= Nn) return;
    int e = g_off[node];
    const int end = g_off[node + 1];
    float4 acc = make_float4(0.f, 0.f, 0.f, 0.f);

    for (; e + 4 <= end; e += 4) {
        uint2 r0 = g_rec[e],     r1 = g_rec[e + 1];
        uint2 r2 = g_rec[e + 2], r3 = g_rec[e + 3];
        float4 v0 = __ldg(&h4[(size_t)r0.x * 16 + p]);
        float4 v1 = __ldg(&h4[(size_t)r1.x * 16 + p]);
        float4 v2 = __ldg(&h4[(size_t)r2.x * 16 + p]);
        float4 v3 = __ldg(&h4[(size_t)r3.x * 16 + p]);
        float w0 = __uint_as_float(r0.y), w1 = __uint_as_float(r1.y);
        float w2 = __uint_as_float(r2.y), w3 = __uint_as_float(r3.y);
        acc.x = fmaf(v0.x, w0, acc.x); acc.y = fmaf(v0.y, w0, acc.y);
        acc.z = fmaf(v0.z, w0, acc.z); acc.w = fmaf(v0.w, w0, acc.w);
        acc.x = fmaf(v1.x, w1, acc.x); acc.y = fmaf(v1.y, w1, acc.y);
        acc.z = fmaf(v1.z, w1, acc.z); acc.w = fmaf(v1.w, w1, acc.w);
        acc.x = fmaf(v2.x, w2, acc.x); acc.y = fmaf(v2.y, w2, acc.y);
        acc.z = fmaf(v2.z, w2, acc.z); acc.w = fmaf(v2.w, w2, acc.w);
        acc.x = fmaf(v3.x, w3, acc.x); acc.y = fmaf(v3.y, w3, acc.y);
        acc.z = fmaf(v3.z, w3, acc.z); acc.w = fmaf(v3.w, w3, acc.w);
    }
    for (; e < end; e++) {
        uint2 r = g_rec[e];
        float4 v = __ldg(&h4[(size_t)r.x * 16 + p]);
        float w = __uint_as_float(r.y);
        acc.x = fmaf(v.x, w, acc.x); acc.y = fmaf(v.y, w, acc.y);
        acc.z = fmaf(v.z, w, acc.z); acc.w = fmaf(v.w, w, acc.w);
    }
    g_hnew4[node * 16 + p] = acc;
}

// ---------------------------------------------------------------------------
// prep — fp16 weight image, GROUPED col order [r|z|i_n|h_n], + biases.
// ---------------------------------------------------------------------------
__global__ void prep_kernel(const float* __restrict__ Wih,
                            const float* __restrict__ Whh,
                            const float* __restrict__ bih,
                            const float* __restrict__ bhh) {
    int idx = blockIdx.x * blockDim.x + threadIdx.x;
    if (idx < 8192) {
        int colp = idx >> 5, q = idx & 31;
        int g = colp >> 6, j = colp & 63;
        int kk = (q & 15) * 4;
        bool isX = (q < 16);
        float4 v = make_float4(0.f, 0.f, 0.f, 0.f);
        const float* srcRow = nullptr;
        if (g == 0)      srcRow = isX ? &Wih[j * 64]         : &Whh[j * 64];
        else if (g == 1) srcRow = isX ? &Wih[(64 + j) * 64]  : &Whh[(64 + j) * 64];
        else if (g == 2) srcRow = isX ? &Wih[(128 + j) * 64] : nullptr;
        else             srcRow = isX ? nullptr              : &Whh[(128 + j) * 64];
        if (srcRow) v = *(const float4*)(srcRow + kk);

        uint32_t h01 = cvth2(v.y, v.x), h23 = cvth2(v.w, v.z);
        uint32_t off = (uint32_t)colp * STRIDE_A + ((q >> 1) << 4) + ((q & 1) << 3);
        *(uint2*)(g_Bimg + off) = make_uint2(h01, h23);
    }
    if (idx < 64) {
        g_biasf[idx]       = bih[idx] + bhh[idx];
        g_biasf[64 + idx]  = bih[64 + idx] + bhh[64 + idx];
        g_biasf[128 + idx] = bih[128 + idx];
        g_biasf[192 + idx] = bhh[128 + idx];
    }
}

// ---------------------------------------------------------------------------
// GEMM + GRU epilogue: 768 threads (24 warps = 6 QUADS) per CTA.
// Quad shares one 16-row A tile; warp qpar owns j in [16*qpar, 16*qpar+16)
// across ALL 4 gates (granules g*4+qpar). 32 accumulators/thread ->
// ~70 regs -> 6 warps/SMSP.
// ---------------------------------------------------------------------------
__global__ void __launch_bounds__(768, 1)
gemm_gru_kernel(const float4* __restrict__ h4, float* __restrict__ out,
                int Nn, int n_tiles16) {
    extern __shared__ __align__(16) char smem[];
    const uint32_t sb = smem_u32(smem);
    const int tid = threadIdx.x;
    const int w = tid >> 5, l = tid & 31;
    const int quad = w >> 2, qpar = w & 3;
    const int t4 = tid & 127;                 // thread-in-quad
    const int r0q = l >> 2, tg = l & 3;
    const int barid = quad + 1;

    // --- B image + bias -> SMEM ---
    {
        const uint4* srcB = (const uint4*)g_Bimg;
        uint4* dstB = (uint4*)(smem + SM_B);
        for (int i = tid; i < B_IMG / 16; i += 768) dstB[i] = srcB[i];
        if (tid < 256) ((float*)smem)[tid] = g_biasf[tid];
    }
    __syncthreads();

    const int quadA_off = SM_A + quad * A_WARP;
    const int sel = l >> 3;
    const uint32_t a_base = sb + (uint32_t)quadA_off +
        (uint32_t)((((sel & 1) << 3) + (l & 7)) * STRIDE_A + ((sel >> 1) << 4));
    // warp's B base: granule (g*4 + qpar) -> offset qpar*16*STRIDE_A + g*64*STRIDE_A
    const uint32_t b_base = sb + SM_B + (uint32_t)qpar * (16 * STRIDE_A) +
        (uint32_t)((((sel >> 1) << 3) + (l & 7)) * STRIDE_A + ((sel & 1) << 4));

    for (int tw = blockIdx.x * N_QUAD + quad; tw < n_tiles16;
         tw += gridDim.x * N_QUAD) {
        const int m0 = tw << 4;

        // --- A tile (16 rows, quad-shared): f32 -> fp16 hi/lo split ---
        // 128 threads x 4 iters: row = ii*4 + (t4>>5), kq = t4&31
#pragma unroll
        for (int ii = 0; ii < 4; ii++) {
            int row = ii * 4 + (t4 >> 5);
            int node = m0 + row;
            int kq = t4 & 31;                         // <16: hnew, >=16: h
            float4 v = make_float4(0.f, 0.f, 0.f, 0.f);
            if (node < Nn)
                v = (kq < 16) ? g_hnew4[node * 16 + kq]
                              : __ldg(&h4[node * 16 + (kq - 16)]);
            uint32_t h01 = cvth2(v.y, v.x), h23 = cvth2(v.w, v.z);
            uint32_t l01 = cvth2(v.y - f16hi_f(h01), v.x - f16lo_f(h01));
            uint32_t l23 = cvth2(v.w - f16hi_f(h23), v.z - f16lo_f(h23));
            uint32_t off = (uint32_t)quadA_off + (uint32_t)row * STRIDE_A +
                           ((uint32_t)(kq >> 1) << 4) + ((uint32_t)(kq & 1) << 3);
            *(uint2*)(smem + off)            = make_uint2(h01, h23);
            *(uint2*)(smem + off + A_HALF_W) = make_uint2(l01, l23);
        }
        QUAD_BAR(barid);          // A tile complete for all 4 warps

        float acc[32];
#pragma unroll
        for (int i = 0; i < 32; i++) acc[i] = 0.f;

        // ---- fp16 2-pass GEMM; gates g: 0=r 1=z 2=i_n(k<64) 3=h_n(k>=64) ----
#pragma unroll 1
        for (int s = 0; s < 4; s++) {
            uint32_t ah0, ah1, ah2, ah3, al0, al1, al2, al3;
            LDSM4(ah0, ah1, ah2, ah3, a_base + (uint32_t)s * 32);
            LDSM4(al0, al1, al2, al3, a_base + A_HALF_W + (uint32_t)s * 32);
#pragma unroll
            for (int g = 0; g < 3; g++) {             // r, z, i_n
                uint32_t b0, b1, b2, b3;
                LDSM4(b0, b1, b2, b3,
                      b_base + (uint32_t)g * (64 * STRIDE_A) + (uint32_t)s * 32);
                float* c0 = &acc[g * 8];
                float* c1 = &acc[g * 8 + 4];
                MMA16816(c0, ah0, ah1, ah2, ah3, b0, b1);
                MMA16816(c1, ah0, ah1, ah2, ah3, b2, b3);
                MMA16816(c0, al0, al1, al2, al3, b0, b1);
                MMA16816(c1, al0, al1, al2, al3, b2, b3);
            }
        }
#pragma unroll 1
        for (int s = 4; s < 8; s++) {
            uint32_t ah0, ah1, ah2, ah3, al0, al1, al2, al3;
            LDSM4(ah0, ah1, ah2, ah3, a_base + (uint32_t)s * 32);
            LDSM4(al0, al1, al2, al3, a_base + A_HALF_W + (uint32_t)s * 32);
#pragma unroll
            for (int q = 0; q < 3; q++) {
                int g = (q < 2) ? q : 3;              // r, z, h_n
                uint32_t b0, b1, b2, b3;
                LDSM4(b0, b1, b2, b3,
                      b_base + (uint32_t)g * (64 * STRIDE_A) + (uint32_t)s * 32);
                float* c0 = &acc[g * 8];
                float* c1 = &acc[g * 8 + 4];
                MMA16816(c0, ah0, ah1, ah2, ah3, b0, b1);
                MMA16816(c1, ah0, ah1, ah2, ah3, b2, b3);
                MMA16816(c0, al0, al1, al2, al3, b0, b1);
                MMA16816(c1, al0, al1, al2, al3, b2, b3);
            }
        }

        // --- Epilogue phase 1: gate math; j = 16*qpar + 8f + 2tg + b ---
#pragma unroll
        for (int f = 0; f < 2; f++) {
            const int jbase = 16 * qpar + 8 * f + 2 * tg;
            float2 br = *(const float2*)(smem + SM_BIAS + jbase * 4);
            float2 bz = *(const float2*)(smem + SM_BIAS + 256 + jbase * 4);
            float2 bi = *(const float2*)(smem + SM_BIAS + 512 + jbase * 4);
            float2 bh = *(const float2*)(smem + SM_BIAS + 768 + jbase * 4);
#pragma unroll
            for (int rs = 0; rs < 2; rs++) {
                const int node_local = r0q + rs * 8;
#pragma unroll
                for (int b = 0; b < 2; b++) {
                    int j = jbase + b;
                    int ai = f * 4 + 2 * rs + b;
                    float rp = acc[ai];
                    float zp = acc[8 + ai];
                    float ip = acc[16 + ai];
                    float hp = acc[24 + ai];
                    float rr = sigmoidf_fast(rp + (b ? br.y : br.x));
                    float zz = sigmoidf_fast(zp + (b ? bz.y : bz.x));
                    float nn = tanhf_fast(ip + (b ? bi.y : bi.x) +
                                          rr * (hp + (b ? bh.y : bh.x)));
                    int kcol = 64 + j;
                    uint32_t hoff = (uint32_t)quadA_off +
                                    (uint32_t)node_local * STRIDE_A +
                                    ((uint32_t)(kcol >> 3) << 4) +
                                    ((uint32_t)(kcol & 7) << 1);
                    uint32_t hib = *(const unsigned short*)(smem + hoff);
                    uint32_t lob = *(const unsigned short*)(smem + hoff + A_HALF_W);
                    float hv = f16lo_f(hib) + f16lo_f(lob);
                    acc[ai] = (1.f - zz) * nn + zz * hv;
                }
            }
        }
        QUAD_BAR(barid);          // all A reads done before staging overwrite

        // --- Phase 2: stage float2 into quad staging (XOR swizzle, 8B units) ---
#pragma unroll
        for (int f = 0; f < 2; f++) {
#pragma unroll
            for (int rs = 0; rs < 2; rs++) {
                const int row = r0q + rs * 8;
                uint32_t u8 = (uint32_t)(8 * qpar + 4 * f + tg);
                uint32_t sa = (uint32_t)quadA_off + (uint32_t)row * 256 +
                              ((u8 ^ (((uint32_t)row & 7) << 2)) << 3);
                *(float2*)(smem + sa) =
                    make_float2(acc[f * 4 + 2 * rs], acc[f * 4 + 2 * rs + 1]);
            }
        }
        QUAD_BAR(barid);          // staging complete

        // --- Phase 3: coalesced 16B stores (128 threads x 2 iters) ---
#pragma unroll
        for (int it = 0; it < 2; it++) {
            int idx = it * 128 + t4;
            int nl = idx >> 4, c16 = idx & 15;
            uint32_t ra = (uint32_t)quadA_off + (uint32_t)nl * 256 +
                          ((((uint32_t)(2 * c16)) ^ (((uint32_t)nl & 7) << 2)) << 3);
            float4 v = *(const float4*)(smem + ra);
            int node = m0 + nl;
            if (node < Nn) *(float4*)(out + (size_t)node * 64 + c16 * 4) = v;
        }
        QUAD_BAR(barid);          // stores done before next tile's A-prep
    }
}

// ---------------------------------------------------------------------------
// Launch
// ---------------------------------------------------------------------------
extern "C" void kernel_launch(void* const* d_in, const int* in_sizes, int n_in,
                              void* d_out, int out_size) {
    const float* h   = (const float*)d_in[0];
    const float* ew  = (const float*)d_in[1];
    const float* Wih = (const float*)d_in[2];
    const float* Whh = (const float*)d_in[3];
    const float* bih = (const float*)d_in[4];
    const float* bhh = (const float*)d_in[5];
    const void* srcp = d_in[6];
    const void* dstp = d_in[7];
    float* out       = (float*)d_out;

    int E  = in_sizes[1];
    int Nn = in_sizes[0] / D;
    int n_tiles16 = (Nn + 15) / 16;
    int eblocks = (E + 255) / 256;
    int nb = (Nn + 1023) / 1024;

    zcnt_kernel<<<(Nn + 255) / 256, 256>>>((const unsigned long long*)srcp,
                                           (const unsigned long long*)dstp, Nn);
    hist_kernel<<<eblocks, 256>>>(dstp, E);
    scanA_kernel<<<nb, 1024>>>(Nn);
    scanC_kernel<<<(Nn + 255) / 256, 256>>>(Nn, E);
    reorder_kernel<<<eblocks, 256>>>(srcp, dstp, ew, E);

    prep_kernel<<<32, 256>>>(Wih, Whh, bih, bhh);

    accum_kernel<<<(Nn * 16 + 255) / 256, 256>>>((const float4*)h, Nn);

    cudaFuncSetAttribute(gemm_gru_kernel,
                         cudaFuncAttributeMaxDynamicSharedMemorySize, SM_TOT);
    gemm_gru_kernel<<<148, 768, SM_TOT>>>((const float4*)h, out, Nn, n_tiles16);
}